// round 14
// baseline (speedup 1.0000x reference)
#include <cuda_runtime.h>
#include <math.h>

#define NB_MAX 400
#define WKER   0.05f
#define INV_WKER 20.0f
#define CUT    0.225f          // 4.5 sigma truncation
#define GNORM  7.9788456080f   // 1/(0.05*sqrt(2*pi))
#define PI_F   3.14159265358979f
#define HF     0.01f           // fine-bin width = sigma/5
#define INV_HF 100.0f
#define MFINE_MAX 1152

__device__ float    g_fine[MFINE_MAX]; // CIC pair cloud (zero at load; phase2b re-zeroes)
__device__ float    g_A[NB_MAX];       // integrand weights (phase 2a -> 2b)
__device__ unsigned g_c1, g_c2, g_c3;  // barrier counters (zero at load; self-reset)

// ---------------------------------------------------------------------------
// ONE persistent kernel. grid = (N+1)/2 = 512 blocks x 256 thr; launch_bounds
// (256,4) caps regs at 64 so all 512 blocks are co-resident (148 SMs x 4) and
// the atomic spin barriers cannot deadlock.
//  phase 1 : MIC pair distances + CIC deposit (block = rows b and N-1-b)
//  barrier : counter c1
//  phase 2a: gather conv -> G(r) -> out, A_k -> g_A      (blocks < nb)
//  barrier : counter c2
//  phase 2b: S(Q), F(Q) -> out (blocks < nb); others re-zero g_fine
//  epilogue: last block resets c1,c2,c3 for the next graph replay
// ---------------------------------------------------------------------------
__global__ void __launch_bounds__(256, 4)
fused_kernel(const float* __restrict__ pos, const float* __restrict__ cell,
             const float* __restrict__ rb,  const float* __restrict__ qb,
             float* __restrict__ out, int N, int nb, float n_pairs)
{
    __shared__ float s_fine[MFINE_MAX];
    __shared__ float s_red[8];
    const int t   = threadIdx.x;
    const int bid = blockIdx.x;
    const unsigned GRID = gridDim.x;

    for (int k = t; k < MFINE_MAX; k += 256) s_fine[k] = 0.0f;

    // uniform cell handling (redundant per thread -> uniform registers)
    float m[9];
    #pragma unroll
    for (int i = 0; i < 9; i++) m[i] = __ldg(cell + i);
    const bool diag = (m[1]==0.f && m[2]==0.f && m[3]==0.f &&
                       m[5]==0.f && m[6]==0.f && m[7]==0.f);
    float ci[9];
    {
        float c00 =  (m[4]*m[8] - m[5]*m[7]);
        float c01 = -(m[3]*m[8] - m[5]*m[6]);
        float c02 =  (m[3]*m[7] - m[4]*m[6]);
        float det = m[0]*c00 + m[1]*c01 + m[2]*c02;
        float id  = 1.0f / det;
        ci[0]=c00*id; ci[1]=-(m[1]*m[8]-m[2]*m[7])*id; ci[2]= (m[1]*m[5]-m[2]*m[4])*id;
        ci[3]=c01*id; ci[4]= (m[0]*m[8]-m[2]*m[6])*id; ci[5]=-(m[0]*m[5]-m[2]*m[3])*id;
        ci[6]=c02*id; ci[7]=-(m[0]*m[7]-m[1]*m[6])*id; ci[8]= (m[0]*m[4]-m[1]*m[3])*id;
    }
    const float L2x = 0.5f*m[0], L2y = 0.5f*m[4], L2z = 0.5f*m[8];

    const float minb  = __ldg(rb)          - 3.0f * WKER;
    const float maxb  = __ldg(rb + nb - 1) + 3.0f * WKER;
    const float minb2 = (minb > 0.0f) ? minb * minb : -1.0f;
    const float maxb2 = maxb * maxb;
    int M = (int)ceilf(maxb * INV_HF) + 1;
    if (M > MFINE_MAX) M = MFINE_MAX;
    const int Mm2 = M - 2;

    __syncthreads();

    // ====================== phase 1: pair histogram =======================
    const float4* __restrict__ p4 = (const float4*)pos;
    float xi = 0.f, yi = 0.f, zi = 0.f;

    auto dopair = [&](float xj, float yj, float zj) {
        float d2;
        if (diag) {
            // |dx_mic| = L/2 - ||dx| - L/2|  (abs = free src modifier)
            float ax = fabsf(xj - xi) - L2x;
            float ay = fabsf(yj - yi) - L2y;
            float az = fabsf(zj - zi) - L2z;
            float bx = L2x - fabsf(ax);
            float by = L2y - fabsf(ay);
            float bz = L2z - fabsf(az);
            d2 = bx*bx + by*by + bz*bz;
        } else {
            float dx = xj-xi, dy = yj-yi, dz = zj-zi;
            float fx = dx*ci[0] + dy*ci[3] + dz*ci[6];
            float fy = dx*ci[1] + dy*ci[4] + dz*ci[7];
            float fz = dx*ci[2] + dy*ci[5] + dz*ci[8];
            fx -= rintf(fx); fy -= rintf(fy); fz -= rintf(fz);
            float mx = fx*m[0] + fy*m[3] + fz*m[6];
            float my = fx*m[1] + fy*m[4] + fz*m[7];
            float mz = fx*m[2] + fy*m[5] + fz*m[8];
            d2 = mx*mx + my*my + mz*mz;
        }
        if (d2 > minb2 && d2 < maxb2) {          // exact reference window
            float dd = d2 + 1e-10f;
            float d  = dd * rsqrtf(dd);
            float u  = fmaf(d, INV_HF, -0.5f);
            int  ml  = __float2int_rd(u);
            float f  = u - (float)ml;
            if (ml > Mm2) ml = Mm2;
            int  m0  = ml > 0 ? ml : 0;
            atomicAdd(&s_fine[m0],     1.0f - f);
            atomicAdd(&s_fine[ml + 1], f);
        }
    };

    #pragma unroll
    for (int h = 0; h < 2; h++) {
        int i = h ? (N - 1 - bid) : bid;
        if (h && i <= bid) continue;             // middle-row guard
        if (i < 0 || i >= N - 1) continue;
        xi = __ldg(pos + 3*i); yi = __ldg(pos + 3*i + 1); zi = __ldg(pos + 3*i + 2);

        int j0 = i + 1;
        int c0 = (j0 + 3) & ~3;
        int Nc = N & ~3;
        { int j = j0 + t;
          if (j < c0 && j < N)
              dopair(__ldg(pos+3*j), __ldg(pos+3*j+1), __ldg(pos+3*j+2)); }
        #pragma unroll 2
        for (int c = c0 + 4*t; c < Nc; c += 1024) {
            int b3 = 3 * (c >> 2);
            float4 q0 = __ldg(p4 + b3);
            float4 q1 = __ldg(p4 + b3 + 1);
            float4 q2 = __ldg(p4 + b3 + 2);
            dopair(q0.x, q0.y, q0.z);
            dopair(q0.w, q1.x, q1.y);
            dopair(q1.z, q1.w, q2.x);
            dopair(q2.y, q2.z, q2.w);
        }
        { int ts = Nc > c0 ? Nc : c0; int j = ts + t;
          if (j < N)
              dopair(__ldg(pos+3*j), __ldg(pos+3*j+1), __ldg(pos+3*j+2)); }
    }
    __syncthreads();
    for (int k = t; k < M; k += 256) {
        float v = s_fine[k];
        if (v != 0.0f) atomicAdd(&g_fine[k], v);
    }

    // ---------------- grid barrier 1 ----------------
    __threadfence();
    __syncthreads();
    if (t == 0) {
        atomicAdd(&g_c1, 1u);
        while (atomicAdd(&g_c1, 0u) < GRID) __nanosleep(64);
    }
    __syncthreads();
    __threadfence();

    // ====================== phase 2a: convolution =========================
    if (bid < nb) {
        float r = __ldg(rb + bid);
        int mlo = (int)ceilf ((r - CUT) * INV_HF - 0.5f);
        int mhi = (int)floorf((r + CUT) * INV_HF - 0.5f);
        mlo = mlo < 0 ? 0 : mlo;
        mhi = mhi > M - 1 ? M - 1 : mhi;
        float acc = 0.0f;
        for (int mm = mlo + t; mm <= mhi; mm += 256) {
            float c = ((float)mm + 0.5f) * HF;
            float u = (r - c) * INV_WKER;
            acc += __ldcg(&g_fine[mm]) * __expf(-0.5f * u * u);
        }
        #pragma unroll
        for (int o = 16; o > 0; o >>= 1) acc += __shfl_xor_sync(0xffffffff, acc, o);
        if ((t & 31) == 0) s_red[t >> 5] = acc;
        __syncthreads();
        if (t == 0) {
            float hist = GNORM * (s_red[0]+s_red[1]+s_red[2]+s_red[3]
                                 +s_red[4]+s_red[5]+s_red[6]+s_red[7]);
            float det = m[0]*(m[4]*m[8]-m[5]*m[7]) - m[1]*(m[3]*m[8]-m[5]*m[6])
                      + m[2]*(m[3]*m[7]-m[4]*m[6]);
            float vol   = fabsf(det);
            float pref  = vol / n_pairs / (4.0f * PI_F);
            float coeff = 5.803f * 5.803f * 0.01f;
            float rho4p = 4.0f * PI_F * ((float)N / vol);
            float G = coeff * (pref * hist / (r * r) - 1.0f);
            out[bid] = G;
            float xm = (bid > 0)      ? __ldg(rb + bid - 1) : r;
            float xp = (bid < nb - 1) ? __ldg(rb + bid + 1) : r;
            g_A[bid] = rho4p * 0.5f * (xp - xm) * r * G;
        }
    }

    // ---------------- grid barrier 2 ----------------
    __threadfence();
    __syncthreads();
    if (t == 0) {
        atomicAdd(&g_c2, 1u);
        while (atomicAdd(&g_c2, 0u) < GRID) __nanosleep(64);
    }
    __syncthreads();
    __threadfence();

    // ====================== phase 2b: S(Q), F(Q) ==========================
    if (bid < nb) {
        float Q    = __ldg(qb + bid);
        float invq = 1.0f / (Q + 1e-10f);
        float acc  = 0.0f;
        for (int k = t; k < nb; k += 256)
            acc += __ldcg(&g_A[k]) * sinf(Q * __ldg(rb + k));
        #pragma unroll
        for (int o = 16; o > 0; o >>= 1) acc += __shfl_xor_sync(0xffffffff, acc, o);
        if ((t & 31) == 0) s_red[t >> 5] = acc;
        __syncthreads();
        if (t == 0) {
            float S = 1.0f + invq * (s_red[0]+s_red[1]+s_red[2]+s_red[3]
                                    +s_red[4]+s_red[5]+s_red[6]+s_red[7]);
            out[nb + bid]     = S;
            out[2 * nb + bid] = Q * (S - 1.0f);
        }
    } else {
        // re-zero the fine histogram for the next graph replay
        for (int k = (bid - nb) * 256 + t; k < MFINE_MAX; k += ((int)GRID - nb) * 256)
            g_fine[k] = 0.0f;
    }

    // ---------------- epilogue: reset barrier counters ----------------
    __syncthreads();
    if (t == 0) {
        __threadfence();
        unsigned v = atomicAdd(&g_c3, 1u);
        if (v == GRID - 1u) {            // last block: everyone is past c2
            atomicExch(&g_c1, 0u);
            atomicExch(&g_c2, 0u);
            atomicExch(&g_c3, 0u);
        }
    }
}

// ---------------------------------------------------------------------------
extern "C" void kernel_launch(void* const* d_in, const int* in_sizes, int n_in,
                              void* d_out, int out_size) {
    const float* pos  = (const float*)d_in[0];
    const float* cell = (const float*)d_in[1];
    const float* rb   = (const float*)d_in[2];
    const float* qb   = (const float*)d_in[3];
    float* out = (float*)d_out;

    int N  = in_sizes[0] / 3;
    int nb = in_sizes[2];
    float n_pairs = 0.5f * (float)N * (float)(N - 1);

    int grid = (N + 1) / 2;   // 512 for N=1024; all co-resident at 4 blocks/SM
    fused_kernel<<<grid, 256>>>(pos, cell, rb, qb, out, N, nb, n_pairs);
}

// round 17
// speedup vs baseline: 1.5979x; 1.5979x over previous
#include <cuda_runtime.h>
#include <math.h>

#define NB_MAX 400
#define WKER   0.05f
#define INV_WKER 20.0f
#define CUT    0.225f          // 4.5 sigma truncation
#define GNORM  7.9788456080f   // 1/(0.05*sqrt(2*pi))
#define PI_F   3.14159265358979f
#define HF     0.01f           // fine-bin width = sigma/5
#define INV_HF 100.0f
#define MFINE_MAX 1152

__device__ float g_fine[MFINE_MAX];   // CIC pair cloud (zero at load; sf re-zeroes)
__device__ float g_A[NB_MAX];         // integrand weights (written by conv)

// ---------------------------------------------------------------------------
// Kernel 1: MIC pair distances + CIC deposit into per-block shared fine
// histogram, then coalesced distinct-address global merge.
// Static balance: block b owns rows b and N-1-b -> exactly N-1 pairs/block.
// float4 position loads (3x LDG.128 per 4 atoms), abs-fold MIC for diagonal
// cells, rsqrt-based distance.
// ---------------------------------------------------------------------------
__global__ void __launch_bounds__(256)
hist_kernel(const float* __restrict__ pos, const float* __restrict__ cell,
            const float* __restrict__ rb, int N, int nb) {
    __shared__ float s_fine[MFINE_MAX];
    const int t   = threadIdx.x;
    const int bid = blockIdx.x;

    for (int k = t; k < MFINE_MAX; k += 256) s_fine[k] = 0.0f;

    // uniform per-thread cell handling (ptxas promotes to uniform regs)
    float m[9];
    #pragma unroll
    for (int i = 0; i < 9; i++) m[i] = __ldg(cell + i);
    const bool diag = (m[1]==0.f && m[2]==0.f && m[3]==0.f &&
                       m[5]==0.f && m[6]==0.f && m[7]==0.f);
    float ci[9];
    {
        float c00 =  (m[4]*m[8] - m[5]*m[7]);
        float c01 = -(m[3]*m[8] - m[5]*m[6]);
        float c02 =  (m[3]*m[7] - m[4]*m[6]);
        float det = m[0]*c00 + m[1]*c01 + m[2]*c02;
        float id  = 1.0f / det;
        ci[0]=c00*id; ci[1]=-(m[1]*m[8]-m[2]*m[7])*id; ci[2]= (m[1]*m[5]-m[2]*m[4])*id;
        ci[3]=c01*id; ci[4]= (m[0]*m[8]-m[2]*m[6])*id; ci[5]=-(m[0]*m[5]-m[2]*m[3])*id;
        ci[6]=c02*id; ci[7]=-(m[0]*m[7]-m[1]*m[6])*id; ci[8]= (m[0]*m[4]-m[1]*m[3])*id;
    }
    const float L2x = 0.5f*m[0], L2y = 0.5f*m[4], L2z = 0.5f*m[8];

    const float minb  = __ldg(rb)          - 3.0f * WKER;
    const float maxb  = __ldg(rb + nb - 1) + 3.0f * WKER;
    const float minb2 = (minb > 0.0f) ? minb * minb : -1.0f;
    const float maxb2 = maxb * maxb;
    int M = (int)ceilf(maxb * INV_HF) + 1;
    if (M > MFINE_MAX) M = MFINE_MAX;
    const int Mm2 = M - 2;

    __syncthreads();

    const float4* __restrict__ p4 = (const float4*)pos;
    float xi = 0.f, yi = 0.f, zi = 0.f;

    auto dopair = [&](float xj, float yj, float zj) {
        float d2;
        if (diag) {
            // |dx_mic| = L/2 - ||dx| - L/2|   (abs = free source modifier)
            float ax = fabsf(xj - xi) - L2x;
            float ay = fabsf(yj - yi) - L2y;
            float az = fabsf(zj - zi) - L2z;
            float bx = L2x - fabsf(ax);
            float by = L2y - fabsf(ay);
            float bz = L2z - fabsf(az);
            d2 = bx*bx + by*by + bz*bz;
        } else {
            float dx = xj-xi, dy = yj-yi, dz = zj-zi;
            float fx = dx*ci[0] + dy*ci[3] + dz*ci[6];
            float fy = dx*ci[1] + dy*ci[4] + dz*ci[7];
            float fz = dx*ci[2] + dy*ci[5] + dz*ci[8];
            fx -= rintf(fx); fy -= rintf(fy); fz -= rintf(fz);
            float mx = fx*m[0] + fy*m[3] + fz*m[6];
            float my = fx*m[1] + fy*m[4] + fz*m[7];
            float mz = fx*m[2] + fy*m[5] + fz*m[8];
            d2 = mx*mx + my*my + mz*mz;
        }
        if (d2 > minb2 && d2 < maxb2) {          // exact reference window
            float dd = d2 + 1e-10f;
            float d  = dd * rsqrtf(dd);
            float u  = fmaf(d, INV_HF, -0.5f);
            int  ml  = __float2int_rd(u);
            float f  = u - (float)ml;
            if (ml > Mm2) ml = Mm2;
            int  m0  = ml > 0 ? ml : 0;
            atomicAdd(&s_fine[m0],     1.0f - f);
            atomicAdd(&s_fine[ml + 1], f);
        }
    };

    #pragma unroll
    for (int h = 0; h < 2; h++) {
        int i = h ? (N - 1 - bid) : bid;
        if (h && i <= bid) continue;             // middle-row guard
        if (i < 0 || i >= N - 1) continue;
        xi = __ldg(pos + 3*i); yi = __ldg(pos + 3*i + 1); zi = __ldg(pos + 3*i + 2);

        int j0 = i + 1;
        int c0 = (j0 + 3) & ~3;                  // first 4-aligned atom
        int Nc = N & ~3;

        { int j = j0 + t;                         // scalar preamble
          if (j < c0 && j < N)
              dopair(__ldg(pos+3*j), __ldg(pos+3*j+1), __ldg(pos+3*j+2)); }

        #pragma unroll 2
        for (int c = c0 + 4*t; c < Nc; c += 1024) {
            int b3 = 3 * (c >> 2);
            float4 q0 = __ldg(p4 + b3);
            float4 q1 = __ldg(p4 + b3 + 1);
            float4 q2 = __ldg(p4 + b3 + 2);
            dopair(q0.x, q0.y, q0.z);
            dopair(q0.w, q1.x, q1.y);
            dopair(q1.z, q1.w, q2.x);
            dopair(q2.y, q2.z, q2.w);
        }

        { int ts = Nc > c0 ? Nc : c0; int j = ts + t;   // scalar tail
          if (j < N)
              dopair(__ldg(pos+3*j), __ldg(pos+3*j+1), __ldg(pos+3*j+2)); }
    }
    __syncthreads();

    // coalesced, distinct-address merge into global
    for (int k = t; k < M; k += 256) {
        float v = s_fine[k];
        if (v != 0.0f) atomicAdd(&g_fine[k], v);
    }
}

// ---------------------------------------------------------------------------
// Kernel 2: gather convolution + G + integrand weights.
//   hist_k = GNORM * sum_m fine[m] * exp(-0.5*((r_k-c_m)/w)^2), |r_k-c_m|<=CUT
//   G_k    = coeff * (vol/n_pairs * hist_k / (4 pi r_k^2) - 1)   -> out[k]
//   A_k    = 4 pi rho * w_k * r_k * G_k                          -> g_A[k]
// ---------------------------------------------------------------------------
__global__ void __launch_bounds__(128)
conv_kernel(const float* __restrict__ cell, const float* __restrict__ rb,
            float* __restrict__ out, int nb, int N, float n_pairs) {
    __shared__ float s_red[4];
    int k = blockIdx.x;
    int t = threadIdx.x;
    float r = __ldg(rb + k);
    float maxb = __ldg(rb + nb - 1) + 3.0f * WKER;
    int M = (int)ceilf(maxb * INV_HF) + 1;
    if (M > MFINE_MAX) M = MFINE_MAX;

    int mlo = (int)ceilf ((r - CUT) * INV_HF - 0.5f);
    int mhi = (int)floorf((r + CUT) * INV_HF - 0.5f);
    mlo = mlo < 0 ? 0 : mlo;
    mhi = mhi > M - 1 ? M - 1 : mhi;

    float acc = 0.0f;
    for (int mm = mlo + t; mm <= mhi; mm += 128) {
        float c = ((float)mm + 0.5f) * HF;
        float u = (r - c) * INV_WKER;
        acc += g_fine[mm] * __expf(-0.5f * u * u);
    }
    #pragma unroll
    for (int o = 16; o > 0; o >>= 1)
        acc += __shfl_xor_sync(0xffffffff, acc, o);
    if ((t & 31) == 0) s_red[t >> 5] = acc;
    __syncthreads();
    if (t == 0) {
        float hist = GNORM * (s_red[0] + s_red[1] + s_red[2] + s_red[3]);
        float m0 = cell[0], m1 = cell[1], m2 = cell[2];
        float m3 = cell[3], m4 = cell[4], m5 = cell[5];
        float m6 = cell[6], m7 = cell[7], m8 = cell[8];
        float det = m0*(m4*m8 - m5*m7) - m1*(m3*m8 - m5*m6) + m2*(m3*m7 - m4*m6);
        float vol = fabsf(det);
        float pref  = vol / n_pairs / (4.0f * PI_F);
        float coeff = 5.803f * 5.803f * 0.01f;
        float rho4p = 4.0f * PI_F * ((float)N / vol);
        float G = coeff * (pref * hist / (r * r) - 1.0f);
        out[k] = G;
        float xm = (k > 0)      ? __ldg(rb + k - 1) : r;
        float xp = (k < nb - 1) ? __ldg(rb + k + 1) : r;
        g_A[k] = rho4p * 0.5f * (xp - xm) * r * G;
    }
}

// ---------------------------------------------------------------------------
// Kernel 3: S(Q) = 1 + (1/(Q+1e-10)) * sum_k A_k sin(Q r_k); F = Q (S-1).
// Also re-zeroes g_fine for the next graph replay.
// ---------------------------------------------------------------------------
__global__ void __launch_bounds__(128)
sf_kernel(const float* __restrict__ rb, const float* __restrict__ qb,
          float* __restrict__ out, int nb) {
    __shared__ float s_red[4];
    int q = blockIdx.x;
    int t = threadIdx.x;

    {   // reset fine histogram (first 9 blocks cover 1152 entries)
        int idx = q * 128 + t;
        if (idx < MFINE_MAX) g_fine[idx] = 0.0f;
    }

    float Q    = __ldg(qb + q);
    float invq = 1.0f / (Q + 1e-10f);
    float acc  = 0.0f;
    for (int k = t; k < nb; k += 128)
        acc += g_A[k] * sinf(Q * __ldg(rb + k));

    #pragma unroll
    for (int o = 16; o > 0; o >>= 1)
        acc += __shfl_xor_sync(0xffffffff, acc, o);
    if ((t & 31) == 0) s_red[t >> 5] = acc;
    __syncthreads();
    if (t == 0) {
        float S = 1.0f + invq * (s_red[0] + s_red[1] + s_red[2] + s_red[3]);
        out[nb + q]     = S;
        out[2 * nb + q] = Q * (S - 1.0f);
    }
}

// ---------------------------------------------------------------------------
extern "C" void kernel_launch(void* const* d_in, const int* in_sizes, int n_in,
                              void* d_out, int out_size) {
    const float* pos  = (const float*)d_in[0];
    const float* cell = (const float*)d_in[1];
    const float* rb   = (const float*)d_in[2];
    const float* qb   = (const float*)d_in[3];
    float* out = (float*)d_out;

    int N  = in_sizes[0] / 3;
    int nb = in_sizes[2];
    float n_pairs = 0.5f * (float)N * (float)(N - 1);

    hist_kernel<<<(N + 1) / 2, 256>>>(pos, cell, rb, N, nb);
    conv_kernel<<<nb, 128>>>(cell, rb, out, nb, N, n_pairs);
    sf_kernel<<<nb, 128>>>(rb, qb, out, nb);
}